// round 4
// baseline (speedup 1.0000x reference)
#include <cuda_runtime.h>
#include <cstdint>

#define N_NODES 100000
#define N_EDGES 1600000
#define IN_F    256
#define HID     128
#define OUTF    64

// Scratch (device globals: allocation-free per harness rules)
__device__ float g_h1[(size_t)N_NODES * HID];   // X@W1
__device__ float g_h2[(size_t)N_NODES * HID];   // A @ h1
__device__ float g_h4[(size_t)N_NODES * OUTF];  // relu(h2+b1)@W2
__device__ int   g_cnt[N_NODES];                // per-row edge count
__device__ int   g_off[N_NODES + 1];            // CSR offsets
__device__ int   g_cur[N_NODES];                // scatter cursors
__device__ int2  g_ecv[N_EDGES];                // CSR-ordered (col, val_bits)

__device__ __forceinline__ uint32_t f2tf32(float f) {
    uint32_t u;
    asm("cvt.rna.tf32.f32 %0, %1;" : "=r"(u) : "f"(f));
    return u;
}

__device__ __forceinline__ void mma_tf32(float c[4], const uint32_t a[4], const uint32_t b[2]) {
    asm volatile(
        "mma.sync.aligned.m16n8k8.row.col.f32.tf32.tf32.f32 "
        "{%0,%1,%2,%3}, {%4,%5,%6,%7}, {%8,%9}, {%0,%1,%2,%3};"
        : "+f"(c[0]), "+f"(c[1]), "+f"(c[2]), "+f"(c[3])
        : "r"(a[0]), "r"(a[1]), "r"(a[2]), "r"(a[3]), "r"(b[0]), "r"(b[1]));
}

// ===========================================================================
// CSR build
// ===========================================================================
__global__ void csr_zero_kernel() {
    int i = blockIdx.x * blockDim.x + threadIdx.x;
    if (i < N_NODES) g_cnt[i] = 0;
}

__global__ void csr_count_kernel(const int* __restrict__ row) {
    int e = blockIdx.x * blockDim.x + threadIdx.x;
    if (e < N_EDGES) atomicAdd(&g_cnt[__ldg(row + e)], 1);
}

// Single block, 1024 threads; each thread scans a contiguous chunk.
__global__ __launch_bounds__(1024) void csr_scan_kernel() {
    __shared__ int ssum[1024];
    const int t  = threadIdx.x;
    const int CH = (N_NODES + 1023) / 1024;   // 98
    int lo = t * CH;
    int hi = lo + CH; if (hi > N_NODES) hi = N_NODES;
    if (lo > N_NODES) lo = N_NODES;

    int s = 0;
    for (int i = lo; i < hi; i++) s += g_cnt[i];
    ssum[t] = s;
    __syncthreads();

    for (int d = 1; d < 1024; d <<= 1) {
        int add = (t >= d) ? ssum[t - d] : 0;
        __syncthreads();
        ssum[t] += add;
        __syncthreads();
    }

    int run = ssum[t] - s;
    for (int i = lo; i < hi; i++) {
        g_off[i] = run;
        g_cur[i] = run;
        run += g_cnt[i];
    }
    if (t == 1023) g_off[N_NODES] = run;
}

// Scatter edges into CSR order WITH payload: one 8B store per edge.
__global__ void csr_scatter_kernel(const int* __restrict__ row,
                                   const int* __restrict__ col,
                                   const float* __restrict__ vals) {
    int e = blockIdx.x * blockDim.x + threadIdx.x;
    if (e < N_EDGES) {
        int r = __ldg(row + e);
        int p = atomicAdd(&g_cur[r], 1);
        g_ecv[p] = make_int2(__ldg(col + e), __float_as_int(__ldg(vals + e)));
    }
}

// ===========================================================================
// GEMM1 (TF32 tensor): g_h1[M,128] = X[M,256] @ W1[256,128]
// ===========================================================================
#define G1_STRIDE 132
__global__ __launch_bounds__(256) void gemm1_tf32_kernel(const float* __restrict__ X,
                                                         const float* __restrict__ W1) {
    __shared__ uint32_t As[32 * G1_STRIDE];
    __shared__ uint32_t Bs[32 * G1_STRIDE];

    const int tid  = threadIdx.x;
    const int warp = tid >> 5;
    const int lane = tid & 31;
    const int wm   = warp >> 1;
    const int wn   = warp & 1;
    const int brow = blockIdx.x * 128;
    const int grp  = lane >> 2;
    const int tig  = lane & 3;

    float c[2][8][4];
#pragma unroll
    for (int mt = 0; mt < 2; mt++)
#pragma unroll
        for (int nt = 0; nt < 8; nt++)
#pragma unroll
            for (int i = 0; i < 4; i++) c[mt][nt][i] = 0.f;

    for (int k0 = 0; k0 < IN_F; k0 += 32) {
#pragma unroll
        for (int i = 0; i < 4; i++) {
            int f  = tid + i * 256;
            int r  = f >> 3;
            int kk = (f & 7) << 2;
            int gr = brow + r;
            float4 v = make_float4(0.f, 0.f, 0.f, 0.f);
            if (gr < N_NODES) v = *(const float4*)(X + (size_t)gr * IN_F + k0 + kk);
            As[(kk + 0) * G1_STRIDE + r] = f2tf32(v.x);
            As[(kk + 1) * G1_STRIDE + r] = f2tf32(v.y);
            As[(kk + 2) * G1_STRIDE + r] = f2tf32(v.z);
            As[(kk + 3) * G1_STRIDE + r] = f2tf32(v.w);
        }
#pragma unroll
        for (int i = 0; i < 4; i++) {
            int f  = tid + i * 256;
            int kr = f >> 5;
            int nc = (f & 31) << 2;
            float4 v = *(const float4*)(W1 + (size_t)(k0 + kr) * HID + nc);
            Bs[kr * G1_STRIDE + nc + 0] = f2tf32(v.x);
            Bs[kr * G1_STRIDE + nc + 1] = f2tf32(v.y);
            Bs[kr * G1_STRIDE + nc + 2] = f2tf32(v.z);
            Bs[kr * G1_STRIDE + nc + 3] = f2tf32(v.w);
        }
        __syncthreads();

#pragma unroll
        for (int ks = 0; ks < 32; ks += 8) {
            uint32_t a[2][4], b[8][2];
#pragma unroll
            for (int mt = 0; mt < 2; mt++) {
                int m0 = wm * 32 + mt * 16;
                a[mt][0] = As[(ks + tig) * G1_STRIDE + m0 + grp];
                a[mt][1] = As[(ks + tig) * G1_STRIDE + m0 + grp + 8];
                a[mt][2] = As[(ks + tig + 4) * G1_STRIDE + m0 + grp];
                a[mt][3] = As[(ks + tig + 4) * G1_STRIDE + m0 + grp + 8];
            }
#pragma unroll
            for (int nt = 0; nt < 8; nt++) {
                int n0 = wn * 64 + nt * 8;
                b[nt][0] = Bs[(ks + tig) * G1_STRIDE + n0 + grp];
                b[nt][1] = Bs[(ks + tig + 4) * G1_STRIDE + n0 + grp];
            }
#pragma unroll
            for (int mt = 0; mt < 2; mt++)
#pragma unroll
                for (int nt = 0; nt < 8; nt++)
                    mma_tf32(c[mt][nt], a[mt], b[nt]);
        }
        __syncthreads();
    }

#pragma unroll
    for (int mt = 0; mt < 2; mt++) {
        int r0 = brow + wm * 32 + mt * 16 + grp;
        int r1 = r0 + 8;
#pragma unroll
        for (int nt = 0; nt < 8; nt++) {
            int col = wn * 64 + nt * 8 + 2 * tig;
            if (r0 < N_NODES)
                *(float2*)(g_h1 + (size_t)r0 * HID + col) =
                    make_float2(c[mt][nt][0], c[mt][nt][1]);
            if (r1 < N_NODES)
                *(float2*)(g_h1 + (size_t)r1 * HID + col) =
                    make_float2(c[mt][nt][2], c[mt][nt][3]);
        }
    }
}

// ===========================================================================
// SpMM1 gather, MLP=8: h2[n] = sum vals[e] * h1[col[e]]
// Warp per node; lane owns float4. Payload g_ecv is coalesced.
// ===========================================================================
__global__ void spmm1_gather_kernel() {
    int node = (blockIdx.x * blockDim.x + threadIdx.x) >> 5;
    if (node >= N_NODES) return;
    int lane  = threadIdx.x & 31;
    int start = g_off[node];
    int end   = g_off[node + 1];

    float4 acc = make_float4(0.f, 0.f, 0.f, 0.f);

    for (int base = start; base < end; base += 32) {
        int m = end - base; if (m > 32) m = 32;
        int2 cv = make_int2(0, 0);
        if (lane < m) cv = g_ecv[base + lane];

        for (int t0 = 0; t0 < m; t0 += 8) {
            int g = m - t0; if (g > 8) g = 8;
            float4 s[8];
#pragma unroll
            for (int j = 0; j < 8; j++) {
                int c = __shfl_sync(0xffffffffu, cv.x, t0 + j);
                if (j < g) s[j] = *((const float4*)(g_h1 + (size_t)c * HID) + lane);
            }
#pragma unroll
            for (int j = 0; j < 8; j++) {
                float v = __int_as_float(__shfl_sync(0xffffffffu, cv.y, t0 + j));
                if (j < g) {
                    acc.x = fmaf(v, s[j].x, acc.x);
                    acc.y = fmaf(v, s[j].y, acc.y);
                    acc.z = fmaf(v, s[j].z, acc.z);
                    acc.w = fmaf(v, s[j].w, acc.w);
                }
            }
        }
    }

    *((float4*)(g_h2 + (size_t)node * HID) + lane) = acc;
}

// ===========================================================================
// GEMM2 (TF32, fused bias+relu): g_h4[M,64] = relu(g_h2+b1) @ W2[128,64]
// ===========================================================================
#define G2B_STRIDE 68
__global__ __launch_bounds__(256) void gemm2_tf32_kernel(const float* __restrict__ B1,
                                                         const float* __restrict__ W2) {
    __shared__ uint32_t As[32 * G1_STRIDE];
    __shared__ uint32_t Bs[32 * G2B_STRIDE];
    __shared__ float    b1s[HID];

    const int tid  = threadIdx.x;
    const int warp = tid >> 5;
    const int lane = tid & 31;
    const int wm   = warp >> 1;
    const int wn   = warp & 1;
    const int brow = blockIdx.x * 128;
    const int grp  = lane >> 2;
    const int tig  = lane & 3;

    if (tid < HID) b1s[tid] = B1[tid];
    __syncthreads();

    float c[2][4][4];
#pragma unroll
    for (int mt = 0; mt < 2; mt++)
#pragma unroll
        for (int nt = 0; nt < 4; nt++)
#pragma unroll
            for (int i = 0; i < 4; i++) c[mt][nt][i] = 0.f;

#pragma unroll
    for (int k0 = 0; k0 < HID; k0 += 32) {
#pragma unroll
        for (int i = 0; i < 4; i++) {
            int f  = tid + i * 256;
            int r  = f >> 3;
            int kk = (f & 7) << 2;
            int gr = brow + r;
            float4 v = make_float4(0.f, 0.f, 0.f, 0.f);
            if (gr < N_NODES) {
                v = *(const float4*)(g_h2 + (size_t)gr * HID + k0 + kk);
                v.x = fmaxf(v.x + b1s[k0 + kk + 0], 0.f);
                v.y = fmaxf(v.y + b1s[k0 + kk + 1], 0.f);
                v.z = fmaxf(v.z + b1s[k0 + kk + 2], 0.f);
                v.w = fmaxf(v.w + b1s[k0 + kk + 3], 0.f);
            }
            As[(kk + 0) * G1_STRIDE + r] = f2tf32(v.x);
            As[(kk + 1) * G1_STRIDE + r] = f2tf32(v.y);
            As[(kk + 2) * G1_STRIDE + r] = f2tf32(v.z);
            As[(kk + 3) * G1_STRIDE + r] = f2tf32(v.w);
        }
#pragma unroll
        for (int i = 0; i < 2; i++) {
            int f  = tid + i * 256;
            int kr = f >> 4;
            int nc = (f & 15) << 2;
            float4 v = *(const float4*)(W2 + (size_t)(k0 + kr) * OUTF + nc);
            Bs[kr * G2B_STRIDE + nc + 0] = f2tf32(v.x);
            Bs[kr * G2B_STRIDE + nc + 1] = f2tf32(v.y);
            Bs[kr * G2B_STRIDE + nc + 2] = f2tf32(v.z);
            Bs[kr * G2B_STRIDE + nc + 3] = f2tf32(v.w);
        }
        __syncthreads();

#pragma unroll
        for (int ks = 0; ks < 32; ks += 8) {
            uint32_t a[2][4], b[4][2];
#pragma unroll
            for (int mt = 0; mt < 2; mt++) {
                int m0 = wm * 32 + mt * 16;
                a[mt][0] = As[(ks + tig) * G1_STRIDE + m0 + grp];
                a[mt][1] = As[(ks + tig) * G1_STRIDE + m0 + grp + 8];
                a[mt][2] = As[(ks + tig + 4) * G1_STRIDE + m0 + grp];
                a[mt][3] = As[(ks + tig + 4) * G1_STRIDE + m0 + grp + 8];
            }
#pragma unroll
            for (int nt = 0; nt < 4; nt++) {
                int n0 = wn * 32 + nt * 8;
                b[nt][0] = Bs[(ks + tig) * G2B_STRIDE + n0 + grp];
                b[nt][1] = Bs[(ks + tig + 4) * G2B_STRIDE + n0 + grp];
            }
#pragma unroll
            for (int mt = 0; mt < 2; mt++)
#pragma unroll
                for (int nt = 0; nt < 4; nt++)
                    mma_tf32(c[mt][nt], a[mt], b[nt]);
        }
        __syncthreads();
    }

#pragma unroll
    for (int mt = 0; mt < 2; mt++) {
        int r0 = brow + wm * 32 + mt * 16 + grp;
        int r1 = r0 + 8;
#pragma unroll
        for (int nt = 0; nt < 4; nt++) {
            int col = wn * 32 + nt * 8 + 2 * tig;
            if (r0 < N_NODES)
                *(float2*)(g_h4 + (size_t)r0 * OUTF + col) =
                    make_float2(c[mt][nt][0], c[mt][nt][1]);
            if (r1 < N_NODES)
                *(float2*)(g_h4 + (size_t)r1 * OUTF + col) =
                    make_float2(c[mt][nt][2], c[mt][nt][3]);
        }
    }
}

// ===========================================================================
// SpMM2 gather, MLP=8: out[n] = b2 + sum vals[e] * h4[col[e]]
// Warp per node; lane owns float2.
// ===========================================================================
__global__ void spmm2_gather_kernel(const float* __restrict__ B2,
                                    float* __restrict__ out) {
    int node = (blockIdx.x * blockDim.x + threadIdx.x) >> 5;
    if (node >= N_NODES) return;
    int lane  = threadIdx.x & 31;
    int start = g_off[node];
    int end   = g_off[node + 1];

    float2 acc = *((const float2*)B2 + lane);

    for (int base = start; base < end; base += 32) {
        int m = end - base; if (m > 32) m = 32;
        int2 cv = make_int2(0, 0);
        if (lane < m) cv = g_ecv[base + lane];

        for (int t0 = 0; t0 < m; t0 += 8) {
            int g = m - t0; if (g > 8) g = 8;
            float2 s[8];
#pragma unroll
            for (int j = 0; j < 8; j++) {
                int c = __shfl_sync(0xffffffffu, cv.x, t0 + j);
                if (j < g) s[j] = *((const float2*)(g_h4 + (size_t)c * OUTF) + lane);
            }
#pragma unroll
            for (int j = 0; j < 8; j++) {
                float v = __int_as_float(__shfl_sync(0xffffffffu, cv.y, t0 + j));
                if (j < g) {
                    acc.x = fmaf(v, s[j].x, acc.x);
                    acc.y = fmaf(v, s[j].y, acc.y);
                }
            }
        }
    }

    *((float2*)(out + (size_t)node * OUTF) + lane) = acc;
}

// ===========================================================================
extern "C" void kernel_launch(void* const* d_in, const int* in_sizes, int n_in,
                              void* d_out, int out_size) {
    const float* x       = (const float*)d_in[0];
    const float* w1      = (const float*)d_in[1];
    const float* b1      = (const float*)d_in[2];
    const float* w2      = (const float*)d_in[3];
    const float* b2      = (const float*)d_in[4];
    const int*   adj_row = (const int*)d_in[5];
    const int*   adj_col = (const int*)d_in[6];
    const float* vals    = (const float*)d_in[7];
    float*       out     = (float*)d_out;

    (void)in_sizes; (void)n_in; (void)out_size;

    // CSR build with payload (amortized over both SpMMs)
    csr_zero_kernel<<<(N_NODES + 255) / 256, 256>>>();
    csr_count_kernel<<<(N_EDGES + 255) / 256, 256>>>(adj_row);
    csr_scan_kernel<<<1, 1024>>>();
    csr_scatter_kernel<<<(N_EDGES + 255) / 256, 256>>>(adj_row, adj_col, vals);

    // h1 = X @ W1 (TF32)
    gemm1_tf32_kernel<<<(N_NODES + 127) / 128, 256>>>(x, w1);

    // h2 = A @ h1 (gather, MLP=8, coalesced payload)
    {
        long long threads = (long long)N_NODES * 32;
        spmm1_gather_kernel<<<(unsigned)((threads + 255) / 256), 256>>>();
    }

    // h4 = relu(h2 + b1) @ W2 (TF32)
    gemm2_tf32_kernel<<<(N_NODES + 127) / 128, 256>>>(b1, w2);

    // out = b2 + A @ h4 (gather, MLP=8)
    {
        long long threads = (long long)N_NODES * 32;
        spmm2_gather_kernel<<<(unsigned)((threads + 255) / 256), 256>>>(b2, out);
    }
}

// round 5
// speedup vs baseline: 1.1668x; 1.1668x over previous
#include <cuda_runtime.h>
#include <cstdint>

#define N_NODES 100000
#define N_EDGES 1600000
#define IN_F    256
#define HID     128
#define OUTF    64

// Scratch (device globals: allocation-free per harness rules)
__device__ float g_h1[(size_t)N_NODES * HID];   // X@W1
__device__ float g_h2[(size_t)N_NODES * HID];   // A @ h1
__device__ float g_h4[(size_t)N_NODES * OUTF];  // relu(h2+b1)@W2
__device__ int   g_cnt[N_NODES];                // per-row edge count
__device__ int   g_off[N_NODES + 1];            // CSR offsets
__device__ int   g_cur[N_NODES];                // scatter cursors
__device__ int2  g_ecv[N_EDGES];                // CSR-ordered (col, val_bits)

__device__ __forceinline__ uint32_t f2tf32(float f) {
    uint32_t u;
    asm("cvt.rna.tf32.f32 %0, %1;" : "=r"(u) : "f"(f));
    return u;
}

__device__ __forceinline__ void mma_tf32(float c[4], const uint32_t a[4], const uint32_t b[2]) {
    asm volatile(
        "mma.sync.aligned.m16n8k8.row.col.f32.tf32.tf32.f32 "
        "{%0,%1,%2,%3}, {%4,%5,%6,%7}, {%8,%9}, {%0,%1,%2,%3};"
        : "+f"(c[0]), "+f"(c[1]), "+f"(c[2]), "+f"(c[3])
        : "r"(a[0]), "r"(a[1]), "r"(a[2]), "r"(a[3]), "r"(b[0]), "r"(b[1]));
}

// ===========================================================================
// CSR build
// ===========================================================================
__global__ void csr_zero_kernel() {
    int i = blockIdx.x * blockDim.x + threadIdx.x;
    if (i < N_NODES) g_cnt[i] = 0;
}

__global__ void csr_count_kernel(const int* __restrict__ row) {
    int e = blockIdx.x * blockDim.x + threadIdx.x;
    if (e < N_EDGES) atomicAdd(&g_cnt[__ldg(row + e)], 1);
}

__global__ __launch_bounds__(1024) void csr_scan_kernel() {
    __shared__ int ssum[1024];
    const int t  = threadIdx.x;
    const int CH = (N_NODES + 1023) / 1024;   // 98
    int lo = t * CH;
    int hi = lo + CH; if (hi > N_NODES) hi = N_NODES;
    if (lo > N_NODES) lo = N_NODES;

    int s = 0;
    for (int i = lo; i < hi; i++) s += g_cnt[i];
    ssum[t] = s;
    __syncthreads();

    for (int d = 1; d < 1024; d <<= 1) {
        int add = (t >= d) ? ssum[t - d] : 0;
        __syncthreads();
        ssum[t] += add;
        __syncthreads();
    }

    int run = ssum[t] - s;
    for (int i = lo; i < hi; i++) {
        g_off[i] = run;
        g_cur[i] = run;
        run += g_cnt[i];
    }
    if (t == 1023) g_off[N_NODES] = run;
}

__global__ void csr_scatter_kernel(const int* __restrict__ row,
                                   const int* __restrict__ col,
                                   const float* __restrict__ vals) {
    int e = blockIdx.x * blockDim.x + threadIdx.x;
    if (e < N_EDGES) {
        int r = __ldg(row + e);
        int p = atomicAdd(&g_cur[r], 1);
        g_ecv[p] = make_int2(__ldg(col + e), __float_as_int(__ldg(vals + e)));
    }
}

// ===========================================================================
// GEMM1 (TF32 tensor): g_h1[M,128] = X[M,256] @ W1[256,128]
// ===========================================================================
#define G1_STRIDE 132
__global__ __launch_bounds__(256) void gemm1_tf32_kernel(const float* __restrict__ X,
                                                         const float* __restrict__ W1) {
    __shared__ uint32_t As[32 * G1_STRIDE];
    __shared__ uint32_t Bs[32 * G1_STRIDE];

    const int tid  = threadIdx.x;
    const int warp = tid >> 5;
    const int lane = tid & 31;
    const int wm   = warp >> 1;
    const int wn   = warp & 1;
    const int brow = blockIdx.x * 128;
    const int grp  = lane >> 2;
    const int tig  = lane & 3;

    float c[2][8][4];
#pragma unroll
    for (int mt = 0; mt < 2; mt++)
#pragma unroll
        for (int nt = 0; nt < 8; nt++)
#pragma unroll
            for (int i = 0; i < 4; i++) c[mt][nt][i] = 0.f;

    for (int k0 = 0; k0 < IN_F; k0 += 32) {
#pragma unroll
        for (int i = 0; i < 4; i++) {
            int f  = tid + i * 256;
            int r  = f >> 3;
            int kk = (f & 7) << 2;
            int gr = brow + r;
            float4 v = make_float4(0.f, 0.f, 0.f, 0.f);
            if (gr < N_NODES) v = *(const float4*)(X + (size_t)gr * IN_F + k0 + kk);
            As[(kk + 0) * G1_STRIDE + r] = f2tf32(v.x);
            As[(kk + 1) * G1_STRIDE + r] = f2tf32(v.y);
            As[(kk + 2) * G1_STRIDE + r] = f2tf32(v.z);
            As[(kk + 3) * G1_STRIDE + r] = f2tf32(v.w);
        }
#pragma unroll
        for (int i = 0; i < 4; i++) {
            int f  = tid + i * 256;
            int kr = f >> 5;
            int nc = (f & 31) << 2;
            float4 v = *(const float4*)(W1 + (size_t)(k0 + kr) * HID + nc);
            Bs[kr * G1_STRIDE + nc + 0] = f2tf32(v.x);
            Bs[kr * G1_STRIDE + nc + 1] = f2tf32(v.y);
            Bs[kr * G1_STRIDE + nc + 2] = f2tf32(v.z);
            Bs[kr * G1_STRIDE + nc + 3] = f2tf32(v.w);
        }
        __syncthreads();

#pragma unroll
        for (int ks = 0; ks < 32; ks += 8) {
            uint32_t a[2][4], b[8][2];
#pragma unroll
            for (int mt = 0; mt < 2; mt++) {
                int m0 = wm * 32 + mt * 16;
                a[mt][0] = As[(ks + tig) * G1_STRIDE + m0 + grp];
                a[mt][1] = As[(ks + tig) * G1_STRIDE + m0 + grp + 8];
                a[mt][2] = As[(ks + tig + 4) * G1_STRIDE + m0 + grp];
                a[mt][3] = As[(ks + tig + 4) * G1_STRIDE + m0 + grp + 8];
            }
#pragma unroll
            for (int nt = 0; nt < 8; nt++) {
                int n0 = wn * 64 + nt * 8;
                b[nt][0] = Bs[(ks + tig) * G1_STRIDE + n0 + grp];
                b[nt][1] = Bs[(ks + tig + 4) * G1_STRIDE + n0 + grp];
            }
#pragma unroll
            for (int mt = 0; mt < 2; mt++)
#pragma unroll
                for (int nt = 0; nt < 8; nt++)
                    mma_tf32(c[mt][nt], a[mt], b[nt]);
        }
        __syncthreads();
    }

#pragma unroll
    for (int mt = 0; mt < 2; mt++) {
        int r0 = brow + wm * 32 + mt * 16 + grp;
        int r1 = r0 + 8;
#pragma unroll
        for (int nt = 0; nt < 8; nt++) {
            int col = wn * 64 + nt * 8 + 2 * tig;
            if (r0 < N_NODES)
                *(float2*)(g_h1 + (size_t)r0 * HID + col) =
                    make_float2(c[mt][nt][0], c[mt][nt][1]);
            if (r1 < N_NODES)
                *(float2*)(g_h1 + (size_t)r1 * HID + col) =
                    make_float2(c[mt][nt][2], c[mt][nt][3]);
        }
    }
}

// ===========================================================================
// SpMM1 gather (smem-staged, no shfl, no predication):
// h2[n] = sum vals[e] * h1[col[e]].  Warp per node; lane owns float4.
// ===========================================================================
__global__ __launch_bounds__(256) void spmm1_gather_kernel() {
    __shared__ int2 scv[8][32];   // per-warp staged (col, val_bits)

    int warp = threadIdx.x >> 5;
    int lane = threadIdx.x & 31;
    int node = blockIdx.x * 8 + warp;
    if (node >= N_NODES) return;

    int start = g_off[node];
    int end   = g_off[node + 1];

    float4 acc = make_float4(0.f, 0.f, 0.f, 0.f);

    for (int base = start; base < end; base += 32) {
        int m  = end - base; if (m > 32) m = 32;
        int mp = (m + 7) & ~7;                 // padded to multiple of 8
        int2 cv = make_int2(node, 0);          // pad: valid row, zero weight
        if (lane < m) cv = g_ecv[base + lane];
        scv[warp][lane] = cv;
        __syncwarp();

        for (int t0 = 0; t0 < mp; t0 += 8) {
            float4 s[8];
#pragma unroll
            for (int j = 0; j < 8; j++) {
                int c = scv[warp][t0 + j].x;   // LDS broadcast
                s[j] = *((const float4*)(g_h1 + (size_t)c * HID) + lane);
            }
#pragma unroll
            for (int j = 0; j < 8; j++) {
                float v = __int_as_float(scv[warp][t0 + j].y);
                acc.x = fmaf(v, s[j].x, acc.x);
                acc.y = fmaf(v, s[j].y, acc.y);
                acc.z = fmaf(v, s[j].z, acc.z);
                acc.w = fmaf(v, s[j].w, acc.w);
            }
        }
        __syncwarp();
    }

    *((float4*)(g_h2 + (size_t)node * HID) + lane) = acc;
}

// ===========================================================================
// GEMM2 (TF32, fused bias+relu): g_h4[M,64] = relu(g_h2+b1) @ W2[128,64]
// ===========================================================================
#define G2B_STRIDE 68
__global__ __launch_bounds__(256) void gemm2_tf32_kernel(const float* __restrict__ B1,
                                                         const float* __restrict__ W2) {
    __shared__ uint32_t As[32 * G1_STRIDE];
    __shared__ uint32_t Bs[32 * G2B_STRIDE];
    __shared__ float    b1s[HID];

    const int tid  = threadIdx.x;
    const int warp = tid >> 5;
    const int lane = tid & 31;
    const int wm   = warp >> 1;
    const int wn   = warp & 1;
    const int brow = blockIdx.x * 128;
    const int grp  = lane >> 2;
    const int tig  = lane & 3;

    if (tid < HID) b1s[tid] = B1[tid];
    __syncthreads();

    float c[2][4][4];
#pragma unroll
    for (int mt = 0; mt < 2; mt++)
#pragma unroll
        for (int nt = 0; nt < 4; nt++)
#pragma unroll
            for (int i = 0; i < 4; i++) c[mt][nt][i] = 0.f;

#pragma unroll
    for (int k0 = 0; k0 < HID; k0 += 32) {
#pragma unroll
        for (int i = 0; i < 4; i++) {
            int f  = tid + i * 256;
            int r  = f >> 3;
            int kk = (f & 7) << 2;
            int gr = brow + r;
            float4 v = make_float4(0.f, 0.f, 0.f, 0.f);
            if (gr < N_NODES) {
                v = *(const float4*)(g_h2 + (size_t)gr * HID + k0 + kk);
                v.x = fmaxf(v.x + b1s[k0 + kk + 0], 0.f);
                v.y = fmaxf(v.y + b1s[k0 + kk + 1], 0.f);
                v.z = fmaxf(v.z + b1s[k0 + kk + 2], 0.f);
                v.w = fmaxf(v.w + b1s[k0 + kk + 3], 0.f);
            }
            As[(kk + 0) * G1_STRIDE + r] = f2tf32(v.x);
            As[(kk + 1) * G1_STRIDE + r] = f2tf32(v.y);
            As[(kk + 2) * G1_STRIDE + r] = f2tf32(v.z);
            As[(kk + 3) * G1_STRIDE + r] = f2tf32(v.w);
        }
#pragma unroll
        for (int i = 0; i < 2; i++) {
            int f  = tid + i * 256;
            int kr = f >> 4;
            int nc = (f & 15) << 2;
            float4 v = *(const float4*)(W2 + (size_t)(k0 + kr) * OUTF + nc);
            Bs[kr * G2B_STRIDE + nc + 0] = f2tf32(v.x);
            Bs[kr * G2B_STRIDE + nc + 1] = f2tf32(v.y);
            Bs[kr * G2B_STRIDE + nc + 2] = f2tf32(v.z);
            Bs[kr * G2B_STRIDE + nc + 3] = f2tf32(v.w);
        }
        __syncthreads();

#pragma unroll
        for (int ks = 0; ks < 32; ks += 8) {
            uint32_t a[2][4], b[4][2];
#pragma unroll
            for (int mt = 0; mt < 2; mt++) {
                int m0 = wm * 32 + mt * 16;
                a[mt][0] = As[(ks + tig) * G1_STRIDE + m0 + grp];
                a[mt][1] = As[(ks + tig) * G1_STRIDE + m0 + grp + 8];
                a[mt][2] = As[(ks + tig + 4) * G1_STRIDE + m0 + grp];
                a[mt][3] = As[(ks + tig + 4) * G1_STRIDE + m0 + grp + 8];
            }
#pragma unroll
            for (int nt = 0; nt < 4; nt++) {
                int n0 = wn * 32 + nt * 8;
                b[nt][0] = Bs[(ks + tig) * G2B_STRIDE + n0 + grp];
                b[nt][1] = Bs[(ks + tig + 4) * G2B_STRIDE + n0 + grp];
            }
#pragma unroll
            for (int mt = 0; mt < 2; mt++)
#pragma unroll
                for (int nt = 0; nt < 4; nt++)
                    mma_tf32(c[mt][nt], a[mt], b[nt]);
        }
        __syncthreads();
    }

#pragma unroll
    for (int mt = 0; mt < 2; mt++) {
        int r0 = brow + wm * 32 + mt * 16 + grp;
        int r1 = r0 + 8;
#pragma unroll
        for (int nt = 0; nt < 4; nt++) {
            int col = wn * 32 + nt * 8 + 2 * tig;
            if (r0 < N_NODES)
                *(float2*)(g_h4 + (size_t)r0 * OUTF + col) =
                    make_float2(c[mt][nt][0], c[mt][nt][1]);
            if (r1 < N_NODES)
                *(float2*)(g_h4 + (size_t)r1 * OUTF + col) =
                    make_float2(c[mt][nt][2], c[mt][nt][3]);
        }
    }
}

// ===========================================================================
// SpMM2 gather (smem-staged): out[n] = b2 + sum vals[e] * h4[col[e]]
// Warp per node; lane owns float2.
// ===========================================================================
__global__ __launch_bounds__(256) void spmm2_gather_kernel(const float* __restrict__ B2,
                                                           float* __restrict__ out) {
    __shared__ int2 scv[8][32];

    int warp = threadIdx.x >> 5;
    int lane = threadIdx.x & 31;
    int node = blockIdx.x * 8 + warp;
    if (node >= N_NODES) return;

    int start = g_off[node];
    int end   = g_off[node + 1];

    float2 acc = *((const float2*)B2 + lane);

    for (int base = start; base < end; base += 32) {
        int m  = end - base; if (m > 32) m = 32;
        int mp = (m + 7) & ~7;
        int2 cv = make_int2(node, 0);
        if (lane < m) cv = g_ecv[base + lane];
        scv[warp][lane] = cv;
        __syncwarp();

        for (int t0 = 0; t0 < mp; t0 += 8) {
            float2 s[8];
#pragma unroll
            for (int j = 0; j < 8; j++) {
                int c = scv[warp][t0 + j].x;
                s[j] = *((const float2*)(g_h4 + (size_t)c * OUTF) + lane);
            }
#pragma unroll
            for (int j = 0; j < 8; j++) {
                float v = __int_as_float(scv[warp][t0 + j].y);
                acc.x = fmaf(v, s[j].x, acc.x);
                acc.y = fmaf(v, s[j].y, acc.y);
            }
        }
        __syncwarp();
    }

    *((float2*)(out + (size_t)node * OUTF) + lane) = acc;
}

// ===========================================================================
extern "C" void kernel_launch(void* const* d_in, const int* in_sizes, int n_in,
                              void* d_out, int out_size) {
    const float* x       = (const float*)d_in[0];
    const float* w1      = (const float*)d_in[1];
    const float* b1      = (const float*)d_in[2];
    const float* w2      = (const float*)d_in[3];
    const float* b2      = (const float*)d_in[4];
    const int*   adj_row = (const int*)d_in[5];
    const int*   adj_col = (const int*)d_in[6];
    const float* vals    = (const float*)d_in[7];
    float*       out     = (float*)d_out;

    (void)in_sizes; (void)n_in; (void)out_size;

    // CSR build with payload (amortized over both SpMMs)
    csr_zero_kernel<<<(N_NODES + 255) / 256, 256>>>();
    csr_count_kernel<<<(N_EDGES + 255) / 256, 256>>>(adj_row);
    csr_scan_kernel<<<1, 1024>>>();
    csr_scatter_kernel<<<(N_EDGES + 255) / 256, 256>>>(adj_row, adj_col, vals);

    // h1 = X @ W1 (TF32)
    gemm1_tf32_kernel<<<(N_NODES + 127) / 128, 256>>>(x, w1);

    // h2 = A @ h1 (smem-staged gather)
    spmm1_gather_kernel<<<(N_NODES + 7) / 8, 256>>>();

    // h4 = relu(h2 + b1) @ W2 (TF32)
    gemm2_tf32_kernel<<<(N_NODES + 127) / 128, 256>>>(b1, w2);

    // out = b2 + A @ h4 (smem-staged gather)
    spmm2_gather_kernel<<<(N_NODES + 7) / 8, 256>>>(b2, out);
}